// round 10
// baseline (speedup 1.0000x reference)
#include <cuda_runtime.h>
#include <cuda_bf16.h>
#include <cstdint>

#define N_NODES 10000
#define N_EDGES 320000
#define KDIM 5
#define C_IN 128
#define C_OUT 128
#define KI 640            // KDIM * C_IN
#define M_PAD 10048       // 157 * 64 (zero pad rows stay zero forever)

// ---------------- device scratch (alloc-free) ----------------
__device__ __nv_bfloat16 g_Ahi[(size_t)M_PAD * KI];
__device__ __nv_bfloat16 g_Alo[(size_t)M_PAD * KI];
__device__ __nv_bfloat16 g_Bhi[(size_t)C_OUT * KI];   // [o][ki] K-major (= B col-major)
__device__ __nv_bfloat16 g_Blo[(size_t)C_OUT * KI];
__device__ int g_rowptr[N_NODES + 1];

// ---------------- helpers ----------------
__device__ __forceinline__ unsigned long long pk2(float a, float b) {
    unsigned long long r;
    asm("mov.b64 %0, {%1, %2};" : "=l"(r) : "f"(a), "f"(b));
    return r;
}
__device__ __forceinline__ unsigned long long ffma2(unsigned long long a,
                                                    unsigned long long b,
                                                    unsigned long long c) {
    unsigned long long d;
    asm("fma.rn.f32x2 %0, %1, %2, %3;" : "=l"(d) : "l"(a), "l"(b), "l"(c));
    return d;
}
__device__ __forceinline__ void unpk2(unsigned long long v, float &a, float &b) {
    asm("mov.b64 {%0, %1}, %2;" : "=f"(a), "=f"(b) : "l"(v));
}
__device__ __forceinline__ int detect_stride(const int* __restrict__ w) {
    bool is64 = (w[N_EDGES + 1] == 0) && (w[N_EDGES + 3] == 0) &&
                (w[N_EDGES + 5] == 0) && (w[N_EDGES + 7] == 0);
    return is64 ? 2 : 1;
}
__device__ __forceinline__ uint32_t su32(const void* p) {
    return (uint32_t)__cvta_generic_to_shared(p);
}
__device__ __forceinline__ void cp16(uint32_t dst, const void* src) {
    asm volatile("cp.async.cg.shared.global [%0], [%1], 16;" :: "r"(dst), "l"(src) : "memory");
}
__device__ __forceinline__ void cp_commit() {
    asm volatile("cp.async.commit_group;" ::: "memory");
}
template <int N>
__device__ __forceinline__ void cp_wait() {
    asm volatile("cp.async.wait_group %0;" :: "n"(N) : "memory");
}
__device__ __forceinline__ void ldsm4(uint32_t& r0, uint32_t& r1, uint32_t& r2,
                                      uint32_t& r3, uint32_t saddr) {
    asm volatile("ldmatrix.sync.aligned.m8n8.x4.shared.b16 {%0,%1,%2,%3}, [%4];"
                 : "=r"(r0), "=r"(r1), "=r"(r2), "=r"(r3) : "r"(saddr));
}
// mma.sync bf16: D(f32) += A(bf16) * B(bf16), m16n8k16, A row-major, B col-major
__device__ __forceinline__ void mma16816(float* d, const uint32_t* a, const uint32_t* b) {
    asm volatile(
        "mma.sync.aligned.m16n8k16.row.col.f32.bf16.bf16.f32 "
        "{%0,%1,%2,%3}, {%4,%5,%6,%7}, {%8,%9}, {%0,%1,%2,%3};"
        : "+f"(d[0]), "+f"(d[1]), "+f"(d[2]), "+f"(d[3])
        : "r"(a[0]), "r"(a[1]), "r"(a[2]), "r"(a[3]), "r"(b[0]), "r"(b[1]));
}

// ---------------- Kernel 1: prep = W split-transpose + rowptr scatter ----------
#define WT_BLOCKS 80   // (640/32) * (128/32)
__global__ void prep_kernel(const int* __restrict__ ei, const float* __restrict__ W) {
    if (blockIdx.x < WT_BLOCKS) {
        __shared__ float tile[32][33];
        int bki = blockIdx.x >> 2;        // 0..19  (ki block)
        int bo  = blockIdx.x & 3;         // 0..3   (o block)
        int tx = threadIdx.x & 31;
        int ty = threadIdx.x >> 5;        // 0..7
#pragma unroll
        for (int j = 0; j < 4; j++) {
            int ki = bki * 32 + ty + j * 8;
            tile[ty + j * 8][tx] = W[(size_t)ki * C_OUT + bo * 32 + tx];
        }
        __syncthreads();
#pragma unroll
        for (int j = 0; j < 4; j++) {
            int o  = bo * 32 + ty + j * 8;
            int ki = bki * 32 + tx;
            float w = tile[tx][ty + j * 8];
            __nv_bfloat16 hi = __float2bfloat16(w);
            float lof = w - __bfloat162float(hi);
            g_Bhi[(size_t)o * KI + ki] = hi;
            g_Blo[(size_t)o * KI + ki] = __float2bfloat16(lof);
        }
    } else {
        int idx = (blockIdx.x - WT_BLOCKS) * 256 + threadIdx.x;
        int stride = detect_stride(ei);
        int s_cur = N_NODES;
        if (idx < N_EDGES) s_cur = ei[(size_t)idx * stride];
        int s_prev = __shfl_up_sync(0xFFFFFFFFu, s_cur, 1);
        if (idx <= N_EDGES) {
            if ((threadIdx.x & 31) == 0)
                s_prev = (idx == 0) ? -1 : ei[(size_t)(idx - 1) * stride];
            for (int n = s_prev + 1; n <= s_cur; n++) g_rowptr[n] = idx;
        }
    }
}

// ---------------- Kernel 2: edge accumulation, 2 warps per node ----------------
// Each warp handles 64 channels (half*64 .. half*64+63); lane owns 2 channels.
template <int STRIDE>
__device__ __forceinline__ void edge_accum_body(const float* __restrict__ h,
                                                const float* __restrict__ X,
                                                const int* __restrict__ dstp,
                                                int node, int half, int lane) {
    int start = g_rowptr[node];
    int end   = g_rowptr[node + 1];
    int chan  = half * 64 + lane * 2;
    const float* hb = h + chan;

    unsigned long long acc[KDIM];
#pragma unroll
    for (int k = 0; k < KDIM; k++) acc[k] = 0ull;

    int e = start;
    // head peel to 4-alignment (enables exact float4 tiling of X rows)
    while (e < end && ((e & 3) || (end - e < 4))) {
        int d = dstp[(size_t)e * STRIDE];
        float2 hv = *(const float2*)(hb + (size_t)d * C_IN);
        unsigned long long hp = pk2(hv.x, hv.y);
        const float* xp = X + (size_t)e * KDIM;
#pragma unroll
        for (int k = 0; k < KDIM; k++) {
            float xk = __ldg(xp + k);
            acc[k] = ffma2(pk2(xk, xk), hp, acc[k]);
        }
        e++;
    }
    // main loop: 4 edges per iter, vectorized X (5 x float4 = 20 floats) + dst
    for (; e + 4 <= end; e += 4) {
        int d[4];
        if (STRIDE == 2) {
            uint4 a = *(const uint4*)(dstp + (size_t)e * 2);
            uint4 b = *(const uint4*)(dstp + (size_t)e * 2 + 4);
            d[0] = (int)a.x; d[1] = (int)a.z; d[2] = (int)b.x; d[3] = (int)b.z;
        } else {
            uint4 a = *(const uint4*)(dstp + e);
            d[0] = (int)a.x; d[1] = (int)a.y; d[2] = (int)a.z; d[3] = (int)a.w;
        }
        float4 xv0 = __ldg((const float4*)(X + (size_t)e * KDIM));
        float4 xv1 = __ldg((const float4*)(X + (size_t)e * KDIM) + 1);
        float4 xv2 = __ldg((const float4*)(X + (size_t)e * KDIM) + 2);
        float4 xv3 = __ldg((const float4*)(X + (size_t)e * KDIM) + 3);
        float4 xv4 = __ldg((const float4*)(X + (size_t)e * KDIM) + 4);
        float x[20] = { xv0.x, xv0.y, xv0.z, xv0.w,
                        xv1.x, xv1.y, xv1.z, xv1.w,
                        xv2.x, xv2.y, xv2.z, xv2.w,
                        xv3.x, xv3.y, xv3.z, xv3.w,
                        xv4.x, xv4.y, xv4.z, xv4.w };
        float2 hv[4];
#pragma unroll
        for (int j = 0; j < 4; j++)
            hv[j] = *(const float2*)(hb + (size_t)d[j] * C_IN);
#pragma unroll
        for (int j = 0; j < 4; j++) {
            unsigned long long hp = pk2(hv[j].x, hv[j].y);
#pragma unroll
            for (int k = 0; k < KDIM; k++) {
                float xk = x[j * KDIM + k];
                acc[k] = ffma2(pk2(xk, xk), hp, acc[k]);
            }
        }
    }
    // tail is impossible: head peel guarantees (end - e) % 4 == 0 or e == end
    for (; e < end; e++) {
        int d = dstp[(size_t)e * STRIDE];
        float2 hv = *(const float2*)(hb + (size_t)d * C_IN);
        unsigned long long hp = pk2(hv.x, hv.y);
        const float* xp = X + (size_t)e * KDIM;
#pragma unroll
        for (int k = 0; k < KDIM; k++) {
            float xk = __ldg(xp + k);
            acc[k] = ffma2(pk2(xk, xk), hp, acc[k]);
        }
    }

    // emit bf16 hi/lo pair for this lane's 2 channels, each k
#pragma unroll
    for (int k = 0; k < KDIM; k++) {
        float v0, v1;
        unpk2(acc[k], v0, v1);
        __nv_bfloat162 hi2 = __float22bfloat162_rn(make_float2(v0, v1));
        float l0 = v0 - __bfloat162float(hi2.x);
        float l1 = v1 - __bfloat162float(hi2.y);
        __nv_bfloat162 lo2 = __float22bfloat162_rn(make_float2(l0, l1));
        size_t idx = (size_t)node * KI + k * C_IN + chan;
        *(uint32_t*)(&g_Ahi[idx]) = *(uint32_t*)&hi2;
        *(uint32_t*)(&g_Alo[idx]) = *(uint32_t*)&lo2;
    }
}

__global__ void __launch_bounds__(256)
edge_accum_kernel(const float* __restrict__ h,
                  const float* __restrict__ X,
                  const int* __restrict__ ei) {
    int gwarp = (blockIdx.x * blockDim.x + threadIdx.x) >> 5;
    int lane  = threadIdx.x & 31;
    if (gwarp >= 2 * N_NODES) return;
    int node = gwarp >> 1;
    int half = gwarp & 1;

    int stride = detect_stride(ei);
    const int* dstp = ei + (size_t)N_EDGES * stride;
    if (stride == 2) edge_accum_body<2>(h, X, dstp, node, half, lane);
    else             edge_accum_body<1>(h, X, dstp, node, half, lane);
}

// ---------------- Kernel 3: HMMA bf16-split GEMM, 64x64 tiles, ldmatrix --------
// out(10000x128) = Ahi@Bhi^T + Ahi@Blo^T + Alo@Bhi^T + bias
#define GBM 64
#define GBN 64
#define GBK 32
#define NSTAGE 20            // KI / GBK
#define APITCH 40            // bf16 per row (80 B): ldmatrix phases hit all 32 banks
#define TILE_B (64 * APITCH * 2)         // 5120 B per tile
#define STAGE_B (4 * TILE_B)             // 20480 B
#define GSMEM (3 * STAGE_B)              // 61440 B (3-stage pipeline)

__global__ void __launch_bounds__(128, 2)
gemm_hmma_kernel(const float* __restrict__ bias, float* __restrict__ out) {
    extern __shared__ __align__(16) char smem[];
    __shared__ float sbias[GBN];

    int tid = threadIdx.x;
    int lane = tid & 31, wid = tid >> 5;
    int g = lane >> 2, tg = lane & 3;
    int m0 = blockIdx.x * GBM;
    int n0 = blockIdx.y * GBN;
    int wm0 = (wid & 1) * 32;       // warp tile 32 x 32
    int wn0 = (wid >> 1) * 32;

    if (tid < GBN) sbias[tid] = bias[n0 + tid];

    uint32_t sb = su32(smem);

    // ldmatrix per-lane byte offsets (within a tile)
    int lr = lane & 7;
    int aR = ((lane >> 3) & 1) * 8;
    int aC = (lane >> 4) * 8;
    int bR = (lane >> 4) * 8;
    int bC = ((lane >> 3) & 1) * 8;
    uint32_t offA0 = (uint32_t)(((wm0 +  0 + lr + aR) * APITCH + aC) * 2);
    uint32_t offA1 = (uint32_t)(((wm0 + 16 + lr + aR) * APITCH + aC) * 2);
    uint32_t offB0 = (uint32_t)(((wn0 +  0 + lr + bR) * APITCH + bC) * 2);
    uint32_t offB1 = (uint32_t)(((wn0 + 16 + lr + bR) * APITCH + bC) * 2);

    int sstage = 0;   // smem stage slot for load_stage (explicit wrap, no div)
    auto load_stage = [&](int i) {
        int k0 = i * GBK;
        char* sbuf = smem + sstage * STAGE_B;
        if (++sstage == 3) sstage = 0;
        const __nv_bfloat16* srcs[4] = {
            g_Ahi + (size_t)m0 * KI + k0,
            g_Alo + (size_t)m0 * KI + k0,
            g_Bhi + (size_t)n0 * KI + k0,
            g_Blo + (size_t)n0 * KI + k0 };
#pragma unroll
        for (int t = 0; t < 4; t++) {
            uint32_t dbase = su32(sbuf + t * TILE_B);
            const __nv_bfloat16* src = srcs[t];
#pragma unroll
            for (int j = 0; j < 2; j++) {
                int w = tid + j * 128;          // 0..255
                int r = w >> 2, c = w & 3;
                cp16(dbase + (uint32_t)(r * (APITCH * 2) + c * 16),
                     src + (size_t)r * KI + c * 8);
            }
        }
        cp_commit();
    };

    float acc[2][4][4];
#pragma unroll
    for (int mt = 0; mt < 2; mt++)
#pragma unroll
        for (int nt = 0; nt < 4; nt++)
#pragma unroll
            for (int j = 0; j < 4; j++) acc[mt][nt][j] = 0.0f;

    load_stage(0);
    load_stage(1);

    int cstage = 0;   // compute stage slot
    for (int i = 0; i < NSTAGE; i++) {
        if (i + 2 < NSTAGE)      { load_stage(i + 2); cp_wait<2>(); }
        else if (i + 1 < NSTAGE) { cp_wait<1>(); }
        else                     { cp_wait<0>(); }
        __syncthreads();

        uint32_t base = sb + (uint32_t)(cstage * STAGE_B);
        if (++cstage == 3) cstage = 0;
        uint32_t bAhi = base;
        uint32_t bAlo = base + TILE_B;
        uint32_t bBhi = base + 2 * TILE_B;
        uint32_t bBlo = base + 3 * TILE_B;

#pragma unroll
        for (int kk = 0; kk < GBK; kk += 16) {
            uint32_t ko = (uint32_t)(kk * 2);
            uint32_t ahi[2][4], alo[2][4], bhi[4][2], blo[4][2];
            ldsm4(ahi[0][0], ahi[0][1], ahi[0][2], ahi[0][3], bAhi + offA0 + ko);
            ldsm4(ahi[1][0], ahi[1][1], ahi[1][2], ahi[1][3], bAhi + offA1 + ko);
            ldsm4(alo[0][0], alo[0][1], alo[0][2], alo[0][3], bAlo + offA0 + ko);
            ldsm4(alo[1][0], alo[1][1], alo[1][2], alo[1][3], bAlo + offA1 + ko);
            ldsm4(bhi[0][0], bhi[0][1], bhi[1][0], bhi[1][1], bBhi + offB0 + ko);
            ldsm4(bhi[2][0], bhi[2][1], bhi[3][0], bhi[3][1], bBhi + offB1 + ko);
            ldsm4(blo[0][0], blo[0][1], blo[1][0], blo[1][1], bBlo + offB0 + ko);
            ldsm4(blo[2][0], blo[2][1], blo[3][0], blo[3][1], bBlo + offB1 + ko);
#pragma unroll
            for (int mt = 0; mt < 2; mt++)
#pragma unroll
                for (int nt = 0; nt < 4; nt++) {
                    mma16816(acc[mt][nt], ahi[mt], bhi[nt]);
                    mma16816(acc[mt][nt], ahi[mt], blo[nt]);
                    mma16816(acc[mt][nt], alo[mt], bhi[nt]);
                }
        }
        __syncthreads();
    }

    // epilogue
#pragma unroll
    for (int mt = 0; mt < 2; mt++) {
#pragma unroll
        for (int nt = 0; nt < 4; nt++) {
            int row = m0 + wm0 + mt * 16 + g;
            int colL = wn0 + nt * 8 + tg * 2;
            int col = n0 + colL;
            float b0 = sbias[colL], b1 = sbias[colL + 1];
            if (row < N_NODES) {
                float2 o0 = make_float2(acc[mt][nt][0] + b0, acc[mt][nt][1] + b1);
                *(float2*)(out + (size_t)row * C_OUT + col) = o0;
            }
            if (row + 8 < N_NODES) {
                float2 o1 = make_float2(acc[mt][nt][2] + b0, acc[mt][nt][3] + b1);
                *(float2*)(out + (size_t)(row + 8) * C_OUT + col) = o1;
            }
        }
    }
}

// ---------------- host launch ----------------
extern "C" void kernel_launch(void* const* d_in, const int* in_sizes, int n_in,
                              void* d_out, int out_size) {
    const float* h    = (const float*)d_in[0];
    const float* X    = (const float*)d_in[1];
    const int*   ei   = (const int*)d_in[2];
    const float* W    = (const float*)d_in[4];
    const float* bias = (const float*)d_in[5];
    float* out = (float*)d_out;

    int rp_blocks = (N_EDGES + 1 + 255) / 256;   // 1251
    prep_kernel<<<WT_BLOCKS + rp_blocks, 256>>>(ei, W);
    edge_accum_kernel<<<(2 * N_NODES * 32 + 255) / 256, 256>>>(h, X, ei);
    cudaFuncSetAttribute(gemm_hmma_kernel,
                         cudaFuncAttributeMaxDynamicSharedMemorySize, GSMEM);
    gemm_hmma_kernel<<<dim3(M_PAD / GBM, C_OUT / GBN), 128, GSMEM>>>(bias, out);
}

// round 14
// speedup vs baseline: 1.0758x; 1.0758x over previous
#include <cuda_runtime.h>
#include <cuda_bf16.h>
#include <cstdint>

#define N_NODES 10000
#define N_EDGES 320000
#define KDIM 5
#define C_IN 128
#define C_OUT 128
#define KI 640            // KDIM * C_IN
#define M_PAD 10048       // 157 * 64 (zero pad rows stay zero forever)

// ---------------- device scratch (alloc-free) ----------------
__device__ __nv_bfloat16 g_Ahi[(size_t)M_PAD * KI];
__device__ __nv_bfloat16 g_Alo[(size_t)M_PAD * KI];
__device__ __nv_bfloat16 g_Bhi[(size_t)C_OUT * KI];   // [o][ki] K-major (= B col-major)
__device__ __nv_bfloat16 g_Blo[(size_t)C_OUT * KI];
__device__ int g_rowptr[N_NODES + 1];

// ---------------- helpers ----------------
__device__ __forceinline__ unsigned long long pk2(float a, float b) {
    unsigned long long r;
    asm("mov.b64 %0, {%1, %2};" : "=l"(r) : "f"(a), "f"(b));
    return r;
}
__device__ __forceinline__ unsigned long long ffma2(unsigned long long a,
                                                    unsigned long long b,
                                                    unsigned long long c) {
    unsigned long long d;
    asm("fma.rn.f32x2 %0, %1, %2, %3;" : "=l"(d) : "l"(a), "l"(b), "l"(c));
    return d;
}
__device__ __forceinline__ void unpk2(unsigned long long v, float &a, float &b) {
    asm("mov.b64 {%0, %1}, %2;" : "=f"(a), "=f"(b) : "l"(v));
}
__device__ __forceinline__ int detect_stride(const int* __restrict__ w) {
    bool is64 = (w[N_EDGES + 1] == 0) && (w[N_EDGES + 3] == 0) &&
                (w[N_EDGES + 5] == 0) && (w[N_EDGES + 7] == 0);
    return is64 ? 2 : 1;
}
__device__ __forceinline__ uint32_t su32(const void* p) {
    return (uint32_t)__cvta_generic_to_shared(p);
}
__device__ __forceinline__ void cp16(uint32_t dst, const void* src) {
    asm volatile("cp.async.cg.shared.global [%0], [%1], 16;" :: "r"(dst), "l"(src) : "memory");
}
__device__ __forceinline__ void cp_commit() {
    asm volatile("cp.async.commit_group;" ::: "memory");
}
template <int N>
__device__ __forceinline__ void cp_wait() {
    asm volatile("cp.async.wait_group %0;" :: "n"(N) : "memory");
}
__device__ __forceinline__ void ldsm4(uint32_t& r0, uint32_t& r1, uint32_t& r2,
                                      uint32_t& r3, uint32_t saddr) {
    asm volatile("ldmatrix.sync.aligned.m8n8.x4.shared.b16 {%0,%1,%2,%3}, [%4];"
                 : "=r"(r0), "=r"(r1), "=r"(r2), "=r"(r3) : "r"(saddr));
}
// mma.sync bf16: D(f32) += A(bf16) * B(bf16), m16n8k16, A row-major, B col-major
__device__ __forceinline__ void mma16816(float* d, const uint32_t* a, const uint32_t* b) {
    asm volatile(
        "mma.sync.aligned.m16n8k16.row.col.f32.bf16.bf16.f32 "
        "{%0,%1,%2,%3}, {%4,%5,%6,%7}, {%8,%9}, {%0,%1,%2,%3};"
        : "+f"(d[0]), "+f"(d[1]), "+f"(d[2]), "+f"(d[3])
        : "r"(a[0]), "r"(a[1]), "r"(a[2]), "r"(a[3]), "r"(b[0]), "r"(b[1]));
}

// ---------------- Kernel 1: prep = W split-transpose + rowptr scatter ----------
#define WT_BLOCKS 80   // (640/32) * (128/32)
__global__ void prep_kernel(const int* __restrict__ ei, const float* __restrict__ W) {
    if (blockIdx.x < WT_BLOCKS) {
        __shared__ float tile[32][33];
        int bki = blockIdx.x >> 2;        // 0..19  (ki block)
        int bo  = blockIdx.x & 3;         // 0..3   (o block)
        int tx = threadIdx.x & 31;
        int ty = threadIdx.x >> 5;        // 0..7
#pragma unroll
        for (int j = 0; j < 4; j++) {
            int ki = bki * 32 + ty + j * 8;
            tile[ty + j * 8][tx] = W[(size_t)ki * C_OUT + bo * 32 + tx];
        }
        __syncthreads();
#pragma unroll
        for (int j = 0; j < 4; j++) {
            int o  = bo * 32 + ty + j * 8;
            int ki = bki * 32 + tx;
            float w = tile[tx][ty + j * 8];
            __nv_bfloat16 hi = __float2bfloat16(w);
            float lof = w - __bfloat162float(hi);
            g_Bhi[(size_t)o * KI + ki] = hi;
            g_Blo[(size_t)o * KI + ki] = __float2bfloat16(lof);
        }
    } else {
        int idx = (blockIdx.x - WT_BLOCKS) * 256 + threadIdx.x;
        int stride = detect_stride(ei);
        int s_cur = N_NODES;
        if (idx < N_EDGES) s_cur = ei[(size_t)idx * stride];
        int s_prev = __shfl_up_sync(0xFFFFFFFFu, s_cur, 1);
        if (idx <= N_EDGES) {
            if ((threadIdx.x & 31) == 0)
                s_prev = (idx == 0) ? -1 : ei[(size_t)(idx - 1) * stride];
            for (int n = s_prev + 1; n <= s_cur; n++) g_rowptr[n] = idx;
        }
    }
}

// ---------------- Kernel 2: edge accumulation, 1 warp per node -----------------
// lane owns 4 channels; vectorized X (5 x LDG.128 per 4 edges) and dst loads.
template <int STRIDE>
__device__ __forceinline__ void edge_accum_body(const float* __restrict__ h,
                                                const float* __restrict__ X,
                                                const int* __restrict__ dstp,
                                                int node, int lane) {
    int start = g_rowptr[node];
    int end   = g_rowptr[node + 1];
    const float* hb = h + lane * 4;

    unsigned long long acc[KDIM][2];
#pragma unroll
    for (int k = 0; k < KDIM; k++) { acc[k][0] = 0ull; acc[k][1] = 0ull; }

    int e = start;
    // head peel until e % 4 == 0 (or fewer than 4 edges remain)
    while (e < end && ((e & 3) || (end - e < 4))) {
        int d = dstp[(size_t)e * STRIDE];
        float4 hv = *(const float4*)(hb + (size_t)d * C_IN);
        unsigned long long h01 = pk2(hv.x, hv.y), h23 = pk2(hv.z, hv.w);
        const float* xp = X + (size_t)e * KDIM;
#pragma unroll
        for (int k = 0; k < KDIM; k++) {
            float xk = __ldg(xp + k);
            unsigned long long x2 = pk2(xk, xk);
            acc[k][0] = ffma2(x2, h01, acc[k][0]);
            acc[k][1] = ffma2(x2, h23, acc[k][1]);
        }
        e++;
    }
    // main loop: 4 edges/iter; e % 4 == 0 guarantees 16B alignment of X and dst
    for (; e + 4 <= end; e += 4) {
        int d[4];
        if (STRIDE == 2) {
            uint4 a = __ldg((const uint4*)(dstp + (size_t)e * 2));
            uint4 b = __ldg((const uint4*)(dstp + (size_t)e * 2) + 1);
            d[0] = (int)a.x; d[1] = (int)a.z; d[2] = (int)b.x; d[3] = (int)b.z;
        } else {
            uint4 a = __ldg((const uint4*)(dstp + e));
            d[0] = (int)a.x; d[1] = (int)a.y; d[2] = (int)a.z; d[3] = (int)a.w;
        }
        const float4* xb = (const float4*)(X + (size_t)e * KDIM);
        float4 xv0 = __ldg(xb);
        float4 xv1 = __ldg(xb + 1);
        float4 xv2 = __ldg(xb + 2);
        float4 xv3 = __ldg(xb + 3);
        float4 xv4 = __ldg(xb + 4);
        float x[20] = { xv0.x, xv0.y, xv0.z, xv0.w,
                        xv1.x, xv1.y, xv1.z, xv1.w,
                        xv2.x, xv2.y, xv2.z, xv2.w,
                        xv3.x, xv3.y, xv3.z, xv3.w,
                        xv4.x, xv4.y, xv4.z, xv4.w };
        float4 hv[4];
#pragma unroll
        for (int j = 0; j < 4; j++)
            hv[j] = *(const float4*)(hb + (size_t)d[j] * C_IN);
#pragma unroll
        for (int j = 0; j < 4; j++) {
            unsigned long long h01 = pk2(hv[j].x, hv[j].y);
            unsigned long long h23 = pk2(hv[j].z, hv[j].w);
#pragma unroll
            for (int k = 0; k < KDIM; k++) {
                unsigned long long x2 = pk2(x[j * KDIM + k], x[j * KDIM + k]);
                acc[k][0] = ffma2(x2, h01, acc[k][0]);
                acc[k][1] = ffma2(x2, h23, acc[k][1]);
            }
        }
    }
    // tail: (end - e) in [0, 3] — head peel does NOT make the span a multiple of 4
    for (; e < end; e++) {
        int d = dstp[(size_t)e * STRIDE];
        float4 hv = *(const float4*)(hb + (size_t)d * C_IN);
        unsigned long long h01 = pk2(hv.x, hv.y), h23 = pk2(hv.z, hv.w);
        const float* xp = X + (size_t)e * KDIM;
#pragma unroll
        for (int k = 0; k < KDIM; k++) {
            float xk = __ldg(xp + k);
            unsigned long long x2 = pk2(xk, xk);
            acc[k][0] = ffma2(x2, h01, acc[k][0]);
            acc[k][1] = ffma2(x2, h23, acc[k][1]);
        }
    }

    // emit bf16 hi/lo pairs
#pragma unroll
    for (int k = 0; k < KDIM; k++) {
        float4 v;
        unpk2(acc[k][0], v.x, v.y);
        unpk2(acc[k][1], v.z, v.w);
        size_t idx = (size_t)node * KI + k * C_IN + lane * 4;
        __nv_bfloat162 h01 = __float22bfloat162_rn(make_float2(v.x, v.y));
        __nv_bfloat162 h23 = __float22bfloat162_rn(make_float2(v.z, v.w));
        float l0 = v.x - __bfloat162float(h01.x);
        float l1 = v.y - __bfloat162float(h01.y);
        float l2 = v.z - __bfloat162float(h23.x);
        float l3 = v.w - __bfloat162float(h23.y);
        __nv_bfloat162 lo01 = __float22bfloat162_rn(make_float2(l0, l1));
        __nv_bfloat162 lo23 = __float22bfloat162_rn(make_float2(l2, l3));
        uint2 hs, ls;
        hs.x = *(uint32_t*)&h01; hs.y = *(uint32_t*)&h23;
        ls.x = *(uint32_t*)&lo01; ls.y = *(uint32_t*)&lo23;
        *(uint2*)(&g_Ahi[idx]) = hs;
        *(uint2*)(&g_Alo[idx]) = ls;
    }
}

__global__ void __launch_bounds__(256)
edge_accum_kernel(const float* __restrict__ h,
                  const float* __restrict__ X,
                  const int* __restrict__ ei) {
    int gwarp = (blockIdx.x * blockDim.x + threadIdx.x) >> 5;
    int lane  = threadIdx.x & 31;
    if (gwarp >= N_NODES) return;

    int stride = detect_stride(ei);
    const int* dstp = ei + (size_t)N_EDGES * stride;
    if (stride == 2) edge_accum_body<2>(h, X, dstp, gwarp, lane);
    else             edge_accum_body<1>(h, X, dstp, gwarp, lane);
}

// ---------------- Kernel 3: HMMA bf16-split GEMM, 64x64 tiles, ldmatrix --------
// out(10000x128) = Ahi@Bhi^T + Ahi@Blo^T + Alo@Bhi^T + bias
#define GBM 64
#define GBN 64
#define GBK 32
#define NSTAGE 20            // KI / GBK
#define APITCH 40            // bf16 per row (80 B): ldmatrix phases hit all 32 banks
#define TILE_B (64 * APITCH * 2)         // 5120 B per tile
#define STAGE_B (4 * TILE_B)             // 20480 B
#define GSMEM (3 * STAGE_B)              // 61440 B (3-stage pipeline)

__global__ void __launch_bounds__(128, 2)
gemm_hmma_kernel(const float* __restrict__ bias, float* __restrict__ out) {
    extern __shared__ __align__(16) char smem[];
    __shared__ float sbias[GBN];

    int tid = threadIdx.x;
    int lane = tid & 31, wid = tid >> 5;
    int g = lane >> 2, tg = lane & 3;
    int m0 = blockIdx.x * GBM;
    int n0 = blockIdx.y * GBN;
    int wm0 = (wid & 1) * 32;       // warp tile 32 x 32
    int wn0 = (wid >> 1) * 32;

    if (tid < GBN) sbias[tid] = bias[n0 + tid];

    uint32_t sb = su32(smem);

    // ldmatrix per-lane byte offsets (within a tile)
    int lr = lane & 7;
    int aR = ((lane >> 3) & 1) * 8;
    int aC = (lane >> 4) * 8;
    int bR = (lane >> 4) * 8;
    int bC = ((lane >> 3) & 1) * 8;
    uint32_t offA0 = (uint32_t)(((wm0 +  0 + lr + aR) * APITCH + aC) * 2);
    uint32_t offA1 = (uint32_t)(((wm0 + 16 + lr + aR) * APITCH + aC) * 2);
    uint32_t offB0 = (uint32_t)(((wn0 +  0 + lr + bR) * APITCH + bC) * 2);
    uint32_t offB1 = (uint32_t)(((wn0 + 16 + lr + bR) * APITCH + bC) * 2);

    int sstage = 0;   // smem stage slot for load_stage (explicit wrap, no div)
    auto load_stage = [&](int i) {
        int k0 = i * GBK;
        char* sbuf = smem + sstage * STAGE_B;
        if (++sstage == 3) sstage = 0;
        const __nv_bfloat16* srcs[4] = {
            g_Ahi + (size_t)m0 * KI + k0,
            g_Alo + (size_t)m0 * KI + k0,
            g_Bhi + (size_t)n0 * KI + k0,
            g_Blo + (size_t)n0 * KI + k0 };
#pragma unroll
        for (int t = 0; t < 4; t++) {
            uint32_t dbase = su32(sbuf + t * TILE_B);
            const __nv_bfloat16* src = srcs[t];
#pragma unroll
            for (int j = 0; j < 2; j++) {
                int w = tid + j * 128;          // 0..255
                int r = w >> 2, c = w & 3;
                cp16(dbase + (uint32_t)(r * (APITCH * 2) + c * 16),
                     src + (size_t)r * KI + c * 8);
            }
        }
        cp_commit();
    };

    float acc[2][4][4];
#pragma unroll
    for (int mt = 0; mt < 2; mt++)
#pragma unroll
        for (int nt = 0; nt < 4; nt++)
#pragma unroll
            for (int j = 0; j < 4; j++) acc[mt][nt][j] = 0.0f;

    load_stage(0);
    load_stage(1);

    int cstage = 0;   // compute stage slot
    for (int i = 0; i < NSTAGE; i++) {
        if (i + 2 < NSTAGE)      { load_stage(i + 2); cp_wait<2>(); }
        else if (i + 1 < NSTAGE) { cp_wait<1>(); }
        else                     { cp_wait<0>(); }
        __syncthreads();

        uint32_t base = sb + (uint32_t)(cstage * STAGE_B);
        if (++cstage == 3) cstage = 0;
        uint32_t bAhi = base;
        uint32_t bAlo = base + TILE_B;
        uint32_t bBhi = base + 2 * TILE_B;
        uint32_t bBlo = base + 3 * TILE_B;

#pragma unroll
        for (int kk = 0; kk < GBK; kk += 16) {
            uint32_t ko = (uint32_t)(kk * 2);
            uint32_t ahi[2][4], alo[2][4], bhi[4][2], blo[4][2];
            ldsm4(ahi[0][0], ahi[0][1], ahi[0][2], ahi[0][3], bAhi + offA0 + ko);
            ldsm4(ahi[1][0], ahi[1][1], ahi[1][2], ahi[1][3], bAhi + offA1 + ko);
            ldsm4(alo[0][0], alo[0][1], alo[0][2], alo[0][3], bAlo + offA0 + ko);
            ldsm4(alo[1][0], alo[1][1], alo[1][2], alo[1][3], bAlo + offA1 + ko);
            ldsm4(bhi[0][0], bhi[0][1], bhi[1][0], bhi[1][1], bBhi + offB0 + ko);
            ldsm4(bhi[2][0], bhi[2][1], bhi[3][0], bhi[3][1], bBhi + offB1 + ko);
            ldsm4(blo[0][0], blo[0][1], blo[1][0], blo[1][1], bBlo + offB0 + ko);
            ldsm4(blo[2][0], blo[2][1], blo[3][0], blo[3][1], bBlo + offB1 + ko);
#pragma unroll
            for (int mt = 0; mt < 2; mt++)
#pragma unroll
                for (int nt = 0; nt < 4; nt++) {
                    mma16816(acc[mt][nt], ahi[mt], bhi[nt]);
                    mma16816(acc[mt][nt], ahi[mt], blo[nt]);
                    mma16816(acc[mt][nt], alo[mt], bhi[nt]);
                }
        }
        __syncthreads();
    }

    // epilogue
#pragma unroll
    for (int mt = 0; mt < 2; mt++) {
#pragma unroll
        for (int nt = 0; nt < 4; nt++) {
            int row = m0 + wm0 + mt * 16 + g;
            int colL = wn0 + nt * 8 + tg * 2;
            int col = n0 + colL;
            float b0 = sbias[colL], b1 = sbias[colL + 1];
            if (row < N_NODES) {
                float2 o0 = make_float2(acc[mt][nt][0] + b0, acc[mt][nt][1] + b1);
                *(float2*)(out + (size_t)row * C_OUT + col) = o0;
            }
            if (row + 8 < N_NODES) {
                float2 o1 = make_float2(acc[mt][nt][2] + b0, acc[mt][nt][3] + b1);
                *(float2*)(out + (size_t)(row + 8) * C_OUT + col) = o1;
            }
        }
    }
}

// ---------------- host launch ----------------
extern "C" void kernel_launch(void* const* d_in, const int* in_sizes, int n_in,
                              void* d_out, int out_size) {
    const float* h    = (const float*)d_in[0];
    const float* X    = (const float*)d_in[1];
    const int*   ei   = (const int*)d_in[2];
    const float* W    = (const float*)d_in[4];
    const float* bias = (const float*)d_in[5];
    float* out = (float*)d_out;

    int rp_blocks = (N_EDGES + 1 + 255) / 256;   // 1251
    prep_kernel<<<WT_BLOCKS + rp_blocks, 256>>>(ei, W);
    edge_accum_kernel<<<(N_NODES * 32 + 255) / 256, 256>>>(h, X, ei);
    cudaFuncSetAttribute(gemm_hmma_kernel,
                         cudaFuncAttributeMaxDynamicSharedMemorySize, GSMEM);
    gemm_hmma_kernel<<<dim3(M_PAD / GBM, C_OUT / GBN), 128, GSMEM>>>(bias, out);
}

// round 16
// speedup vs baseline: 1.1093x; 1.0311x over previous
#include <cuda_runtime.h>
#include <cuda_bf16.h>
#include <cuda_fp16.h>
#include <cstdint>

#define N_NODES 10000
#define N_EDGES 320000
#define KDIM 5
#define C_IN 128
#define C_OUT 128
#define KI 640            // KDIM * C_IN
#define M_PAD 10048       // 157 * 64 (zero pad rows stay zero forever)

// ---------------- device scratch (alloc-free) ----------------
__device__ __nv_bfloat16 g_Ahi[(size_t)M_PAD * KI];
__device__ __nv_bfloat16 g_Alo[(size_t)M_PAD * KI];
__device__ __nv_bfloat16 g_Bhi[(size_t)C_OUT * KI];   // [o][ki] K-major (= B col-major)
__device__ __nv_bfloat16 g_Blo[(size_t)C_OUT * KI];
__device__ __half g_h16[(size_t)N_NODES * C_IN];      // fp16 copy of h (2.56 MB)
__device__ int g_rowptr[N_NODES + 1];

// ---------------- helpers ----------------
__device__ __forceinline__ unsigned long long pk2(float a, float b) {
    unsigned long long r;
    asm("mov.b64 %0, {%1, %2};" : "=l"(r) : "f"(a), "f"(b));
    return r;
}
__device__ __forceinline__ unsigned long long ffma2(unsigned long long a,
                                                    unsigned long long b,
                                                    unsigned long long c) {
    unsigned long long d;
    asm("fma.rn.f32x2 %0, %1, %2, %3;" : "=l"(d) : "l"(a), "l"(b), "l"(c));
    return d;
}
__device__ __forceinline__ void unpk2(unsigned long long v, float &a, float &b) {
    asm("mov.b64 {%0, %1}, %2;" : "=f"(a), "=f"(b) : "l"(v));
}
__device__ __forceinline__ int detect_stride(const int* __restrict__ w) {
    bool is64 = (w[N_EDGES + 1] == 0) && (w[N_EDGES + 3] == 0) &&
                (w[N_EDGES + 5] == 0) && (w[N_EDGES + 7] == 0);
    return is64 ? 2 : 1;
}
__device__ __forceinline__ uint32_t su32(const void* p) {
    return (uint32_t)__cvta_generic_to_shared(p);
}
__device__ __forceinline__ void cp16(uint32_t dst, const void* src) {
    asm volatile("cp.async.cg.shared.global [%0], [%1], 16;" :: "r"(dst), "l"(src) : "memory");
}
__device__ __forceinline__ void cp_commit() {
    asm volatile("cp.async.commit_group;" ::: "memory");
}
template <int N>
__device__ __forceinline__ void cp_wait() {
    asm volatile("cp.async.wait_group %0;" :: "n"(N) : "memory");
}
__device__ __forceinline__ void ldsm4(uint32_t& r0, uint32_t& r1, uint32_t& r2,
                                      uint32_t& r3, uint32_t saddr) {
    asm volatile("ldmatrix.sync.aligned.m8n8.x4.shared.b16 {%0,%1,%2,%3}, [%4];"
                 : "=r"(r0), "=r"(r1), "=r"(r2), "=r"(r3) : "r"(saddr));
}
// mma.sync bf16: D(f32) += A(bf16) * B(bf16), m16n8k16, A row-major, B col-major
__device__ __forceinline__ void mma16816(float* d, const uint32_t* a, const uint32_t* b) {
    asm volatile(
        "mma.sync.aligned.m16n8k16.row.col.f32.bf16.bf16.f32 "
        "{%0,%1,%2,%3}, {%4,%5,%6,%7}, {%8,%9}, {%0,%1,%2,%3};"
        : "+f"(d[0]), "+f"(d[1]), "+f"(d[2]), "+f"(d[3])
        : "r"(a[0]), "r"(a[1]), "r"(a[2]), "r"(a[3]), "r"(b[0]), "r"(b[1]));
}

// ---------------- Kernel 1: prep = W split-transpose + h->fp16 + rowptr --------
#define WT_BLOCKS 80     // (640/32) * (128/32)
#define HCVT_BLOCKS 1250 // 1250*256 threads x 1 float4 = 1,280,000 floats
__global__ void prep_kernel(const int* __restrict__ ei, const float* __restrict__ W,
                            const float* __restrict__ h) {
    if (blockIdx.x < WT_BLOCKS) {
        __shared__ float tile[32][33];
        int bki = blockIdx.x >> 2;        // 0..19  (ki block)
        int bo  = blockIdx.x & 3;         // 0..3   (o block)
        int tx = threadIdx.x & 31;
        int ty = threadIdx.x >> 5;        // 0..7
#pragma unroll
        for (int j = 0; j < 4; j++) {
            int ki = bki * 32 + ty + j * 8;
            tile[ty + j * 8][tx] = W[(size_t)ki * C_OUT + bo * 32 + tx];
        }
        __syncthreads();
#pragma unroll
        for (int j = 0; j < 4; j++) {
            int o  = bo * 32 + ty + j * 8;
            int ki = bki * 32 + tx;
            float w = tile[tx][ty + j * 8];
            __nv_bfloat16 hi = __float2bfloat16(w);
            float lof = w - __bfloat162float(hi);
            g_Bhi[(size_t)o * KI + ki] = hi;
            g_Blo[(size_t)o * KI + ki] = __float2bfloat16(lof);
        }
    } else if (blockIdx.x < WT_BLOCKS + HCVT_BLOCKS) {
        // h -> fp16 conversion, one float4 per thread
        int idx4 = (blockIdx.x - WT_BLOCKS) * 256 + threadIdx.x;   // < 320000
        float4 v = __ldg((const float4*)h + idx4);
        __half2 a = __floats2half2_rn(v.x, v.y);
        __half2 b = __floats2half2_rn(v.z, v.w);
        uint2 packed;
        packed.x = *(uint32_t*)&a;
        packed.y = *(uint32_t*)&b;
        *(uint2*)(g_h16 + (size_t)idx4 * 4) = packed;
    } else {
        int idx = (blockIdx.x - WT_BLOCKS - HCVT_BLOCKS) * 256 + threadIdx.x;
        int stride = detect_stride(ei);
        int s_cur = N_NODES;
        if (idx < N_EDGES) s_cur = ei[(size_t)idx * stride];
        int s_prev = __shfl_up_sync(0xFFFFFFFFu, s_cur, 1);
        if (idx <= N_EDGES) {
            if ((threadIdx.x & 31) == 0)
                s_prev = (idx == 0) ? -1 : ei[(size_t)(idx - 1) * stride];
            for (int n = s_prev + 1; n <= s_cur; n++) g_rowptr[n] = idx;
        }
    }
}

// ---------------- Kernel 2: edge accumulation, 1 warp per node -----------------
// lane owns 4 channels; h gathered in fp16 (8 B/lane), fp32 accumulate.
__device__ __forceinline__ void h16_to_pk(uint2 hv, unsigned long long& h01,
                                          unsigned long long& h23) {
    float2 f01 = __half22float2(*(const __half2*)&hv.x);
    float2 f23 = __half22float2(*(const __half2*)&hv.y);
    h01 = pk2(f01.x, f01.y);
    h23 = pk2(f23.x, f23.y);
}

template <int STRIDE>
__device__ __forceinline__ void edge_accum_body(const float* __restrict__ X,
                                                const int* __restrict__ dstp,
                                                int node, int lane) {
    int start = g_rowptr[node];
    int end   = g_rowptr[node + 1];
    const __half* hb = g_h16 + lane * 4;

    unsigned long long acc[KDIM][2];
#pragma unroll
    for (int k = 0; k < KDIM; k++) { acc[k][0] = 0ull; acc[k][1] = 0ull; }

    int e = start;
    // head peel until e % 4 == 0 (or fewer than 4 edges remain)
    while (e < end && ((e & 3) || (end - e < 4))) {
        int d = dstp[(size_t)e * STRIDE];
        uint2 hv = *(const uint2*)(hb + (size_t)d * C_IN);
        unsigned long long h01, h23;
        h16_to_pk(hv, h01, h23);
        const float* xp = X + (size_t)e * KDIM;
#pragma unroll
        for (int k = 0; k < KDIM; k++) {
            float xk = __ldg(xp + k);
            unsigned long long x2 = pk2(xk, xk);
            acc[k][0] = ffma2(x2, h01, acc[k][0]);
            acc[k][1] = ffma2(x2, h23, acc[k][1]);
        }
        e++;
    }
    // main loop: 4 edges/iter; e % 4 == 0 guarantees 16B alignment of X and dst
    for (; e + 4 <= end; e += 4) {
        int d[4];
        if (STRIDE == 2) {
            uint4 a = __ldg((const uint4*)(dstp + (size_t)e * 2));
            uint4 b = __ldg((const uint4*)(dstp + (size_t)e * 2) + 1);
            d[0] = (int)a.x; d[1] = (int)a.z; d[2] = (int)b.x; d[3] = (int)b.z;
        } else {
            uint4 a = __ldg((const uint4*)(dstp + e));
            d[0] = (int)a.x; d[1] = (int)a.y; d[2] = (int)a.z; d[3] = (int)a.w;
        }
        const float4* xb = (const float4*)(X + (size_t)e * KDIM);
        float4 xv0 = __ldg(xb);
        float4 xv1 = __ldg(xb + 1);
        float4 xv2 = __ldg(xb + 2);
        float4 xv3 = __ldg(xb + 3);
        float4 xv4 = __ldg(xb + 4);
        float x[20] = { xv0.x, xv0.y, xv0.z, xv0.w,
                        xv1.x, xv1.y, xv1.z, xv1.w,
                        xv2.x, xv2.y, xv2.z, xv2.w,
                        xv3.x, xv3.y, xv3.z, xv3.w,
                        xv4.x, xv4.y, xv4.z, xv4.w };
        uint2 hv[4];
#pragma unroll
        for (int j = 0; j < 4; j++)
            hv[j] = *(const uint2*)(hb + (size_t)d[j] * C_IN);
#pragma unroll
        for (int j = 0; j < 4; j++) {
            unsigned long long h01, h23;
            h16_to_pk(hv[j], h01, h23);
#pragma unroll
            for (int k = 0; k < KDIM; k++) {
                unsigned long long x2 = pk2(x[j * KDIM + k], x[j * KDIM + k]);
                acc[k][0] = ffma2(x2, h01, acc[k][0]);
                acc[k][1] = ffma2(x2, h23, acc[k][1]);
            }
        }
    }
    // tail: (end - e) in [0, 3]
    for (; e < end; e++) {
        int d = dstp[(size_t)e * STRIDE];
        uint2 hv = *(const uint2*)(hb + (size_t)d * C_IN);
        unsigned long long h01, h23;
        h16_to_pk(hv, h01, h23);
        const float* xp = X + (size_t)e * KDIM;
#pragma unroll
        for (int k = 0; k < KDIM; k++) {
            float xk = __ldg(xp + k);
            unsigned long long x2 = pk2(xk, xk);
            acc[k][0] = ffma2(x2, h01, acc[k][0]);
            acc[k][1] = ffma2(x2, h23, acc[k][1]);
        }
    }

    // emit bf16 hi/lo pairs
#pragma unroll
    for (int k = 0; k < KDIM; k++) {
        float4 v;
        unpk2(acc[k][0], v.x, v.y);
        unpk2(acc[k][1], v.z, v.w);
        size_t idx = (size_t)node * KI + k * C_IN + lane * 4;
        __nv_bfloat162 h01 = __float22bfloat162_rn(make_float2(v.x, v.y));
        __nv_bfloat162 h23 = __float22bfloat162_rn(make_float2(v.z, v.w));
        float l0 = v.x - __bfloat162float(h01.x);
        float l1 = v.y - __bfloat162float(h01.y);
        float l2 = v.z - __bfloat162float(h23.x);
        float l3 = v.w - __bfloat162float(h23.y);
        __nv_bfloat162 lo01 = __float22bfloat162_rn(make_float2(l0, l1));
        __nv_bfloat162 lo23 = __float22bfloat162_rn(make_float2(l2, l3));
        uint2 hs, ls;
        hs.x = *(uint32_t*)&h01; hs.y = *(uint32_t*)&h23;
        ls.x = *(uint32_t*)&lo01; ls.y = *(uint32_t*)&lo23;
        *(uint2*)(&g_Ahi[idx]) = hs;
        *(uint2*)(&g_Alo[idx]) = ls;
    }
}

__global__ void __launch_bounds__(256)
edge_accum_kernel(const float* __restrict__ X,
                  const int* __restrict__ ei) {
    int gwarp = (blockIdx.x * blockDim.x + threadIdx.x) >> 5;
    int lane  = threadIdx.x & 31;
    if (gwarp >= N_NODES) return;

    int stride = detect_stride(ei);
    const int* dstp = ei + (size_t)N_EDGES * stride;
    if (stride == 2) edge_accum_body<2>(X, dstp, gwarp, lane);
    else             edge_accum_body<1>(X, dstp, gwarp, lane);
}

// ---------------- Kernel 3: HMMA bf16-split GEMM, 64x64 tiles, ldmatrix --------
// out(10000x128) = Ahi@Bhi^T + Ahi@Blo^T + Alo@Bhi^T + bias
#define GBM 64
#define GBN 64
#define GBK 32
#define NSTAGE 20            // KI / GBK
#define APITCH 40            // bf16 per row (80 B): ldmatrix phases hit all 32 banks
#define TILE_B (64 * APITCH * 2)         // 5120 B per tile
#define STAGE_B (4 * TILE_B)             // 20480 B
#define GSMEM (3 * STAGE_B)              // 61440 B (3-stage pipeline)

__global__ void __launch_bounds__(128, 2)
gemm_hmma_kernel(const float* __restrict__ bias, float* __restrict__ out) {
    extern __shared__ __align__(16) char smem[];
    __shared__ float sbias[GBN];

    int tid = threadIdx.x;
    int lane = tid & 31, wid = tid >> 5;
    int g = lane >> 2, tg = lane & 3;
    int m0 = blockIdx.x * GBM;
    int n0 = blockIdx.y * GBN;
    int wm0 = (wid & 1) * 32;       // warp tile 32 x 32
    int wn0 = (wid >> 1) * 32;

    if (tid < GBN) sbias[tid] = bias[n0 + tid];

    uint32_t sb = su32(smem);

    // ldmatrix per-lane byte offsets (within a tile)
    int lr = lane & 7;
    int aR = ((lane >> 3) & 1) * 8;
    int aC = (lane >> 4) * 8;
    int bR = (lane >> 4) * 8;
    int bC = ((lane >> 3) & 1) * 8;
    uint32_t offA0 = (uint32_t)(((wm0 +  0 + lr + aR) * APITCH + aC) * 2);
    uint32_t offA1 = (uint32_t)(((wm0 + 16 + lr + aR) * APITCH + aC) * 2);
    uint32_t offB0 = (uint32_t)(((wn0 +  0 + lr + bR) * APITCH + bC) * 2);
    uint32_t offB1 = (uint32_t)(((wn0 + 16 + lr + bR) * APITCH + bC) * 2);

    int sstage = 0;   // smem stage slot for load_stage (explicit wrap, no div)
    auto load_stage = [&](int i) {
        int k0 = i * GBK;
        char* sbuf = smem + sstage * STAGE_B;
        if (++sstage == 3) sstage = 0;
        const __nv_bfloat16* srcs[4] = {
            g_Ahi + (size_t)m0 * KI + k0,
            g_Alo + (size_t)m0 * KI + k0,
            g_Bhi + (size_t)n0 * KI + k0,
            g_Blo + (size_t)n0 * KI + k0 };
#pragma unroll
        for (int t = 0; t < 4; t++) {
            uint32_t dbase = su32(sbuf + t * TILE_B);
            const __nv_bfloat16* src = srcs[t];
#pragma unroll
            for (int j = 0; j < 2; j++) {
                int w = tid + j * 128;          // 0..255
                int r = w >> 2, c = w & 3;
                cp16(dbase + (uint32_t)(r * (APITCH * 2) + c * 16),
                     src + (size_t)r * KI + c * 8);
            }
        }
        cp_commit();
    };

    float acc[2][4][4];
#pragma unroll
    for (int mt = 0; mt < 2; mt++)
#pragma unroll
        for (int nt = 0; nt < 4; nt++)
#pragma unroll
            for (int j = 0; j < 4; j++) acc[mt][nt][j] = 0.0f;

    load_stage(0);
    load_stage(1);

    int cstage = 0;   // compute stage slot
    for (int i = 0; i < NSTAGE; i++) {
        if (i + 2 < NSTAGE)      { load_stage(i + 2); cp_wait<2>(); }
        else if (i + 1 < NSTAGE) { cp_wait<1>(); }
        else                     { cp_wait<0>(); }
        __syncthreads();

        uint32_t base = sb + (uint32_t)(cstage * STAGE_B);
        if (++cstage == 3) cstage = 0;
        uint32_t bAhi = base;
        uint32_t bAlo = base + TILE_B;
        uint32_t bBhi = base + 2 * TILE_B;
        uint32_t bBlo = base + 3 * TILE_B;

#pragma unroll
        for (int kk = 0; kk < GBK; kk += 16) {
            uint32_t ko = (uint32_t)(kk * 2);
            uint32_t ahi[2][4], alo[2][4], bhi[4][2], blo[4][2];
            ldsm4(ahi[0][0], ahi[0][1], ahi[0][2], ahi[0][3], bAhi + offA0 + ko);
            ldsm4(ahi[1][0], ahi[1][1], ahi[1][2], ahi[1][3], bAhi + offA1 + ko);
            ldsm4(alo[0][0], alo[0][1], alo[0][2], alo[0][3], bAlo + offA0 + ko);
            ldsm4(alo[1][0], alo[1][1], alo[1][2], alo[1][3], bAlo + offA1 + ko);
            ldsm4(bhi[0][0], bhi[0][1], bhi[1][0], bhi[1][1], bBhi + offB0 + ko);
            ldsm4(bhi[2][0], bhi[2][1], bhi[3][0], bhi[3][1], bBhi + offB1 + ko);
            ldsm4(blo[0][0], blo[0][1], blo[1][0], blo[1][1], bBlo + offB0 + ko);
            ldsm4(blo[2][0], blo[2][1], blo[3][0], blo[3][1], bBlo + offB1 + ko);
#pragma unroll
            for (int mt = 0; mt < 2; mt++)
#pragma unroll
                for (int nt = 0; nt < 4; nt++) {
                    mma16816(acc[mt][nt], ahi[mt], bhi[nt]);
                    mma16816(acc[mt][nt], ahi[mt], blo[nt]);
                    mma16816(acc[mt][nt], alo[mt], bhi[nt]);
                }
        }
        __syncthreads();
    }

    // epilogue
#pragma unroll
    for (int mt = 0; mt < 2; mt++) {
#pragma unroll
        for (int nt = 0; nt < 4; nt++) {
            int row = m0 + wm0 + mt * 16 + g;
            int colL = wn0 + nt * 8 + tg * 2;
            int col = n0 + colL;
            float b0 = sbias[colL], b1 = sbias[colL + 1];
            if (row < N_NODES) {
                float2 o0 = make_float2(acc[mt][nt][0] + b0, acc[mt][nt][1] + b1);
                *(float2*)(out + (size_t)row * C_OUT + col) = o0;
            }
            if (row + 8 < N_NODES) {
                float2 o1 = make_float2(acc[mt][nt][2] + b0, acc[mt][nt][3] + b1);
                *(float2*)(out + (size_t)(row + 8) * C_OUT + col) = o1;
            }
        }
    }
}

// ---------------- host launch ----------------
extern "C" void kernel_launch(void* const* d_in, const int* in_sizes, int n_in,
                              void* d_out, int out_size) {
    const float* h    = (const float*)d_in[0];
    const float* X    = (const float*)d_in[1];
    const int*   ei   = (const int*)d_in[2];
    const float* W    = (const float*)d_in[4];
    const float* bias = (const float*)d_in[5];
    float* out = (float*)d_out;

    int rp_blocks = (N_EDGES + 1 + 255) / 256;   // 1251
    prep_kernel<<<WT_BLOCKS + HCVT_BLOCKS + rp_blocks, 256>>>(ei, W, h);
    edge_accum_kernel<<<(N_NODES * 32 + 255) / 256, 256>>>(X, ei);
    cudaFuncSetAttribute(gemm_hmma_kernel,
                         cudaFuncAttributeMaxDynamicSharedMemorySize, GSMEM);
    gemm_hmma_kernel<<<dim3(M_PAD / GBM, C_OUT / GBN), 128, GSMEM>>>(bias, out);
}

// round 17
// speedup vs baseline: 1.4422x; 1.3001x over previous
#include <cuda_runtime.h>
#include <cuda_bf16.h>
#include <cuda_fp16.h>
#include <cstdint>

#define N_NODES 10000
#define N_EDGES 320000
#define KDIM 5
#define C_IN 128
#define C_OUT 128
#define KI 640            // KDIM * C_IN
#define M_PAD 10048       // 157 * 64 (zero pad rows stay zero forever)

// ---------------- device scratch (alloc-free) ----------------
__device__ __half g_A16[(size_t)M_PAD * KI];          // res in fp16 (12.9 MB)
__device__ __half g_B16[(size_t)C_OUT * KI];          // W^T in fp16 [o][ki]
__device__ __half g_h16[(size_t)N_NODES * C_IN];      // fp16 copy of h (2.56 MB)
__device__ int g_rowptr[N_NODES + 1];

// ---------------- helpers ----------------
__device__ __forceinline__ unsigned long long pk2(float a, float b) {
    unsigned long long r;
    asm("mov.b64 %0, {%1, %2};" : "=l"(r) : "f"(a), "f"(b));
    return r;
}
__device__ __forceinline__ unsigned long long ffma2(unsigned long long a,
                                                    unsigned long long b,
                                                    unsigned long long c) {
    unsigned long long d;
    asm("fma.rn.f32x2 %0, %1, %2, %3;" : "=l"(d) : "l"(a), "l"(b), "l"(c));
    return d;
}
__device__ __forceinline__ void unpk2(unsigned long long v, float &a, float &b) {
    asm("mov.b64 {%0, %1}, %2;" : "=f"(a), "=f"(b) : "l"(v));
}
__device__ __forceinline__ int detect_stride(const int* __restrict__ w) {
    bool is64 = (w[N_EDGES + 1] == 0) && (w[N_EDGES + 3] == 0) &&
                (w[N_EDGES + 5] == 0) && (w[N_EDGES + 7] == 0);
    return is64 ? 2 : 1;
}
__device__ __forceinline__ uint32_t su32(const void* p) {
    return (uint32_t)__cvta_generic_to_shared(p);
}
__device__ __forceinline__ void cp16(uint32_t dst, const void* src) {
    asm volatile("cp.async.cg.shared.global [%0], [%1], 16;" :: "r"(dst), "l"(src) : "memory");
}
__device__ __forceinline__ void cp_commit() {
    asm volatile("cp.async.commit_group;" ::: "memory");
}
template <int N>
__device__ __forceinline__ void cp_wait() {
    asm volatile("cp.async.wait_group %0;" :: "n"(N) : "memory");
}
__device__ __forceinline__ void ldsm4(uint32_t& r0, uint32_t& r1, uint32_t& r2,
                                      uint32_t& r3, uint32_t saddr) {
    asm volatile("ldmatrix.sync.aligned.m8n8.x4.shared.b16 {%0,%1,%2,%3}, [%4];"
                 : "=r"(r0), "=r"(r1), "=r"(r2), "=r"(r3) : "r"(saddr));
}
// mma.sync fp16: D(f32) += A(f16) * B(f16), m16n8k16, A row-major, B col-major
__device__ __forceinline__ void mma16816h(float* d, const uint32_t* a, const uint32_t* b) {
    asm volatile(
        "mma.sync.aligned.m16n8k16.row.col.f32.f16.f16.f32 "
        "{%0,%1,%2,%3}, {%4,%5,%6,%7}, {%8,%9}, {%0,%1,%2,%3};"
        : "+f"(d[0]), "+f"(d[1]), "+f"(d[2]), "+f"(d[3])
        : "r"(a[0]), "r"(a[1]), "r"(a[2]), "r"(a[3]), "r"(b[0]), "r"(b[1]));
}

// ---------------- Kernel 1: prep = W fp16-transpose + h->fp16 + rowptr ---------
#define WT_BLOCKS 80     // (640/32) * (128/32)
#define HCVT_BLOCKS 1250 // 1250*256 threads x 1 float4 = 1,280,000 floats
__global__ void prep_kernel(const int* __restrict__ ei, const float* __restrict__ W,
                            const float* __restrict__ h) {
    if (blockIdx.x < WT_BLOCKS) {
        __shared__ float tile[32][33];
        int bki = blockIdx.x >> 2;        // 0..19  (ki block)
        int bo  = blockIdx.x & 3;         // 0..3   (o block)
        int tx = threadIdx.x & 31;
        int ty = threadIdx.x >> 5;        // 0..7
#pragma unroll
        for (int j = 0; j < 4; j++) {
            int ki = bki * 32 + ty + j * 8;
            tile[ty + j * 8][tx] = W[(size_t)ki * C_OUT + bo * 32 + tx];
        }
        __syncthreads();
#pragma unroll
        for (int j = 0; j < 4; j++) {
            int o  = bo * 32 + ty + j * 8;
            int ki = bki * 32 + tx;
            g_B16[(size_t)o * KI + ki] = __float2half_rn(tile[tx][ty + j * 8]);
        }
    } else if (blockIdx.x < WT_BLOCKS + HCVT_BLOCKS) {
        // h -> fp16 conversion, one float4 per thread
        int idx4 = (blockIdx.x - WT_BLOCKS) * 256 + threadIdx.x;   // < 320000
        float4 v = __ldg((const float4*)h + idx4);
        __half2 a = __floats2half2_rn(v.x, v.y);
        __half2 b = __floats2half2_rn(v.z, v.w);
        uint2 packed;
        packed.x = *(uint32_t*)&a;
        packed.y = *(uint32_t*)&b;
        *(uint2*)(g_h16 + (size_t)idx4 * 4) = packed;
    } else {
        int idx = (blockIdx.x - WT_BLOCKS - HCVT_BLOCKS) * 256 + threadIdx.x;
        int stride = detect_stride(ei);
        int s_cur = N_NODES;
        if (idx < N_EDGES) s_cur = ei[(size_t)idx * stride];
        int s_prev = __shfl_up_sync(0xFFFFFFFFu, s_cur, 1);
        if (idx <= N_EDGES) {
            if ((threadIdx.x & 31) == 0)
                s_prev = (idx == 0) ? -1 : ei[(size_t)(idx - 1) * stride];
            for (int n = s_prev + 1; n <= s_cur; n++) g_rowptr[n] = idx;
        }
    }
}

// ---------------- Kernel 2: edge accumulation, 1 warp per node -----------------
// lane owns 4 channels; h gathered in fp16 (8 B/lane), fp32 accumulate.
__device__ __forceinline__ void h16_to_pk(uint2 hv, unsigned long long& h01,
                                          unsigned long long& h23) {
    float2 f01 = __half22float2(*(const __half2*)&hv.x);
    float2 f23 = __half22float2(*(const __half2*)&hv.y);
    h01 = pk2(f01.x, f01.y);
    h23 = pk2(f23.x, f23.y);
}

template <int STRIDE>
__device__ __forceinline__ void edge_accum_body(const float* __restrict__ X,
                                                const int* __restrict__ dstp,
                                                int node, int lane) {
    int start = g_rowptr[node];
    int end   = g_rowptr[node + 1];
    const __half* hb = g_h16 + lane * 4;

    unsigned long long acc[KDIM][2];
#pragma unroll
    for (int k = 0; k < KDIM; k++) { acc[k][0] = 0ull; acc[k][1] = 0ull; }

    int e = start;
    // head peel until e % 4 == 0 (or fewer than 4 edges remain)
    while (e < end && ((e & 3) || (end - e < 4))) {
        int d = dstp[(size_t)e * STRIDE];
        uint2 hv = *(const uint2*)(hb + (size_t)d * C_IN);
        unsigned long long h01, h23;
        h16_to_pk(hv, h01, h23);
        const float* xp = X + (size_t)e * KDIM;
#pragma unroll
        for (int k = 0; k < KDIM; k++) {
            float xk = __ldg(xp + k);
            unsigned long long x2 = pk2(xk, xk);
            acc[k][0] = ffma2(x2, h01, acc[k][0]);
            acc[k][1] = ffma2(x2, h23, acc[k][1]);
        }
        e++;
    }
    // main loop: 4 edges/iter; e % 4 == 0 guarantees 16B alignment of X and dst
    for (; e + 4 <= end; e += 4) {
        int d[4];
        if (STRIDE == 2) {
            uint4 a = __ldg((const uint4*)(dstp + (size_t)e * 2));
            uint4 b = __ldg((const uint4*)(dstp + (size_t)e * 2) + 1);
            d[0] = (int)a.x; d[1] = (int)a.z; d[2] = (int)b.x; d[3] = (int)b.z;
        } else {
            uint4 a = __ldg((const uint4*)(dstp + e));
            d[0] = (int)a.x; d[1] = (int)a.y; d[2] = (int)a.z; d[3] = (int)a.w;
        }
        const float4* xb = (const float4*)(X + (size_t)e * KDIM);
        float4 xv0 = __ldg(xb);
        float4 xv1 = __ldg(xb + 1);
        float4 xv2 = __ldg(xb + 2);
        float4 xv3 = __ldg(xb + 3);
        float4 xv4 = __ldg(xb + 4);
        float x[20] = { xv0.x, xv0.y, xv0.z, xv0.w,
                        xv1.x, xv1.y, xv1.z, xv1.w,
                        xv2.x, xv2.y, xv2.z, xv2.w,
                        xv3.x, xv3.y, xv3.z, xv3.w,
                        xv4.x, xv4.y, xv4.z, xv4.w };
        uint2 hv[4];
#pragma unroll
        for (int j = 0; j < 4; j++)
            hv[j] = *(const uint2*)(hb + (size_t)d[j] * C_IN);
#pragma unroll
        for (int j = 0; j < 4; j++) {
            unsigned long long h01, h23;
            h16_to_pk(hv[j], h01, h23);
#pragma unroll
            for (int k = 0; k < KDIM; k++) {
                unsigned long long x2 = pk2(x[j * KDIM + k], x[j * KDIM + k]);
                acc[k][0] = ffma2(x2, h01, acc[k][0]);
                acc[k][1] = ffma2(x2, h23, acc[k][1]);
            }
        }
    }
    // tail: (end - e) in [0, 3]
    for (; e < end; e++) {
        int d = dstp[(size_t)e * STRIDE];
        uint2 hv = *(const uint2*)(hb + (size_t)d * C_IN);
        unsigned long long h01, h23;
        h16_to_pk(hv, h01, h23);
        const float* xp = X + (size_t)e * KDIM;
#pragma unroll
        for (int k = 0; k < KDIM; k++) {
            float xk = __ldg(xp + k);
            unsigned long long x2 = pk2(xk, xk);
            acc[k][0] = ffma2(x2, h01, acc[k][0]);
            acc[k][1] = ffma2(x2, h23, acc[k][1]);
        }
    }

    // emit fp16 (single store per k)
#pragma unroll
    for (int k = 0; k < KDIM; k++) {
        float4 v;
        unpk2(acc[k][0], v.x, v.y);
        unpk2(acc[k][1], v.z, v.w);
        __half2 p01 = __floats2half2_rn(v.x, v.y);
        __half2 p23 = __floats2half2_rn(v.z, v.w);
        uint2 packed;
        packed.x = *(uint32_t*)&p01;
        packed.y = *(uint32_t*)&p23;
        size_t idx = (size_t)node * KI + k * C_IN + lane * 4;
        *(uint2*)(&g_A16[idx]) = packed;
    }
}

__global__ void __launch_bounds__(256)
edge_accum_kernel(const float* __restrict__ X,
                  const int* __restrict__ ei) {
    int gwarp = (blockIdx.x * blockDim.x + threadIdx.x) >> 5;
    int lane  = threadIdx.x & 31;
    if (gwarp >= N_NODES) return;

    int stride = detect_stride(ei);
    const int* dstp = ei + (size_t)N_EDGES * stride;
    if (stride == 2) edge_accum_body<2>(X, dstp, gwarp, lane);
    else             edge_accum_body<1>(X, dstp, gwarp, lane);
}

// ---------------- Kernel 3: single-pass fp16 HMMA GEMM -------------------------
// out(10000x128) = A16(10000x640) @ B16^T(640x128) + bias
#define GBM 64
#define GBN 64
#define GBK 32
#define NSTAGE 20            // KI / GBK
#define APITCH 40            // fp16 per row (80 B): ldmatrix phases hit all 32 banks
#define TILE_B (64 * APITCH * 2)         // 5120 B per tile
#define STAGE_B (2 * TILE_B)             // 10240 B (A + B tiles)
#define GSMEM (3 * STAGE_B)              // 30720 B (3-stage pipeline)

__global__ void __launch_bounds__(128, 3)
gemm_hmma_kernel(const float* __restrict__ bias, float* __restrict__ out) {
    extern __shared__ __align__(16) char smem[];
    __shared__ float sbias[GBN];

    int tid = threadIdx.x;
    int lane = tid & 31, wid = tid >> 5;
    int g = lane >> 2, tg = lane & 3;
    int m0 = blockIdx.x * GBM;
    int n0 = blockIdx.y * GBN;
    int wm0 = (wid & 1) * 32;       // warp tile 32 x 32
    int wn0 = (wid >> 1) * 32;

    if (tid < GBN) sbias[tid] = bias[n0 + tid];

    uint32_t sb = su32(smem);

    // ldmatrix per-lane byte offsets (within a tile)
    int lr = lane & 7;
    int aR = ((lane >> 3) & 1) * 8;
    int aC = (lane >> 4) * 8;
    int bR = (lane >> 4) * 8;
    int bC = ((lane >> 3) & 1) * 8;
    uint32_t offA0 = (uint32_t)(((wm0 +  0 + lr + aR) * APITCH + aC) * 2);
    uint32_t offA1 = (uint32_t)(((wm0 + 16 + lr + aR) * APITCH + aC) * 2);
    uint32_t offB0 = (uint32_t)(((wn0 +  0 + lr + bR) * APITCH + bC) * 2);
    uint32_t offB1 = (uint32_t)(((wn0 + 16 + lr + bR) * APITCH + bC) * 2);

    int sstage = 0;   // smem stage slot for load_stage (explicit wrap, no div)
    auto load_stage = [&](int i) {
        int k0 = i * GBK;
        char* sbuf = smem + sstage * STAGE_B;
        if (++sstage == 3) sstage = 0;
        const __half* srcs[2] = {
            g_A16 + (size_t)m0 * KI + k0,
            g_B16 + (size_t)n0 * KI + k0 };
#pragma unroll
        for (int t = 0; t < 2; t++) {
            uint32_t dbase = su32(sbuf + t * TILE_B);
            const __half* src = srcs[t];
#pragma unroll
            for (int j = 0; j < 2; j++) {
                int w = tid + j * 128;          // 0..255
                int r = w >> 2, c = w & 3;
                cp16(dbase + (uint32_t)(r * (APITCH * 2) + c * 16),
                     src + (size_t)r * KI + c * 8);
            }
        }
        cp_commit();
    };

    float acc[2][4][4];
#pragma unroll
    for (int mt = 0; mt < 2; mt++)
#pragma unroll
        for (int nt = 0; nt < 4; nt++)
#pragma unroll
            for (int j = 0; j < 4; j++) acc[mt][nt][j] = 0.0f;

    load_stage(0);
    load_stage(1);

    int cstage = 0;   // compute stage slot
    for (int i = 0; i < NSTAGE; i++) {
        if (i + 2 < NSTAGE)      { load_stage(i + 2); cp_wait<2>(); }
        else if (i + 1 < NSTAGE) { cp_wait<1>(); }
        else                     { cp_wait<0>(); }
        __syncthreads();

        uint32_t base = sb + (uint32_t)(cstage * STAGE_B);
        if (++cstage == 3) cstage = 0;
        uint32_t bA = base;
        uint32_t bB = base + TILE_B;

#pragma unroll
        for (int kk = 0; kk < GBK; kk += 16) {
            uint32_t ko = (uint32_t)(kk * 2);
            uint32_t a[2][4], b[4][2];
            ldsm4(a[0][0], a[0][1], a[0][2], a[0][3], bA + offA0 + ko);
            ldsm4(a[1][0], a[1][1], a[1][2], a[1][3], bA + offA1 + ko);
            ldsm4(b[0][0], b[0][1], b[1][0], b[1][1], bB + offB0 + ko);
            ldsm4(b[2][0], b[2][1], b[3][0], b[3][1], bB + offB1 + ko);
#pragma unroll
            for (int mt = 0; mt < 2; mt++)
#pragma unroll
                for (int nt = 0; nt < 4; nt++)
                    mma16816h(acc[mt][nt], a[mt], b[nt]);
        }
        __syncthreads();
    }

    // epilogue
#pragma unroll
    for (int mt = 0; mt < 2; mt++) {
#pragma unroll
        for (int nt = 0; nt < 4; nt++) {
            int row = m0 + wm0 + mt * 16 + g;
            int colL = wn0 + nt * 8 + tg * 2;
            int col = n0 + colL;
            float b0 = sbias[colL], b1 = sbias[colL + 1];
            if (row < N_NODES) {
                float2 o0 = make_float2(acc[mt][nt][0] + b0, acc[mt][nt][1] + b1);
                *(float2*)(out + (size_t)row * C_OUT + col) = o0;
            }
            if (row + 8 < N_NODES) {
                float2 o1 = make_float2(acc[mt][nt][2] + b0, acc[mt][nt][3] + b1);
                *(float2*)(out + (size_t)(row + 8) * C_OUT + col) = o1;
            }
        }
    }
}

// ---------------- host launch ----------------
extern "C" void kernel_launch(void* const* d_in, const int* in_sizes, int n_in,
                              void* d_out, int out_size) {
    const float* h    = (const float*)d_in[0];
    const float* X    = (const float*)d_in[1];
    const int*   ei   = (const int*)d_in[2];
    const float* W    = (const float*)d_in[4];
    const float* bias = (const float*)d_in[5];
    float* out = (float*)d_out;

    int rp_blocks = (N_EDGES + 1 + 255) / 256;   // 1251
    prep_kernel<<<WT_BLOCKS + HCVT_BLOCKS + rp_blocks, 256>>>(ei, W, h);
    edge_accum_kernel<<<(N_NODES * 32 + 255) / 256, 256>>>(X, ei);
    cudaFuncSetAttribute(gemm_hmma_kernel,
                         cudaFuncAttributeMaxDynamicSharedMemorySize, GSMEM);
    gemm_hmma_kernel<<<dim3(M_PAD / GBM, C_OUT / GBN), 128, GSMEM>>>(bias, out);
}